// round 4
// baseline (speedup 1.0000x reference)
#include <cuda_runtime.h>
#include <math.h>

#define EPS 1e-5f
#define MAX_BK 32768
typedef unsigned long long u64;

// ---- scratch (device globals) ----
__device__ float4 g_sums[MAX_BK];           // per-bin {sum fx, sum fy, sum_i, sum_j}
__device__ float  g_cnt [MAX_BK];
__device__ float  g_x  [(size_t)5  * MAX_BK];   // transposed token features [5][BK]
__device__ float  g_t2 [(size_t)32 * MAX_BK];   // transposed layer-2 pre-BN [32][BK]
__device__ float  g_xstat[20];              // Sx(5) + upper-tri Sxx(15)
__device__ float  g_st2[64];                // [0:32) sum, [32:64) sumsq layer-2

__device__ __forceinline__ void red_v4(float4* p, float a, float b, float c, float d) {
    asm volatile("red.global.add.v4.f32 [%0], {%1,%2,%3,%4};"
                 :: "l"(p), "f"(a), "f"(b), "f"(c), "f"(d) : "memory");
}
__device__ __forceinline__ void red_f(float* p, float v) {
    asm volatile("red.global.add.f32 [%0], %1;" :: "l"(p), "f"(v) : "memory");
}

// ---- kernel 0: zero accumulators ----
__global__ void zero_k(int bk) {
    int i = blockIdx.x * blockDim.x + threadIdx.x;
    if (i < bk) { g_sums[i] = make_float4(0.f, 0.f, 0.f, 0.f); g_cnt[i] = 0.f; }
    if (i < 20) g_xstat[i] = 0.f;
    if (i < 64) g_st2[i] = 0.f;
}

// ---- pool (fast path): smem-privatized, 2 packed u64 atomics / pixel ----
// s_xy: lo32 = sum(round(fx*4096)+65536), hi32 = same for fy  (chunk<=16384 -> max 2^31)
// s_ij: [40:64) sum_i, [16:40) sum_j, [0:16) count
#define CHUNK 16384
__global__ void pool_priv_k(const int*   __restrict__ labels,
                            const float* __restrict__ fxp,
                            const float* __restrict__ fyp,
                            int P, int h, int K, int cpb) {
    extern __shared__ char sm[];
    u64* s_ij = (u64*)sm;
    u64* s_xy = (u64*)(sm + (size_t)K * 8);
    int t = threadIdx.x;
    for (int q = t; q < K; q += 256) { s_ij[q] = 0ull; s_xy[q] = 0ull; }
    __syncthreads();

    int b     = blockIdx.x / cpb;
    int chunk = blockIdx.x - b * cpb;
    int base4 = (b * P + chunk * CHUNK) >> 2;
#pragma unroll 4
    for (int it = 0; it < CHUNK / 1024; it++) {
        int g4 = base4 + it * 256 + t;
        int4   lb = ((const int4*)  labels)[g4];
        float4 vx = ((const float4*)fxp)[g4];
        float4 vy = ((const float4*)fyp)[g4];
        int p0  = g4 << 2;
        int pin = p0 - b * P;
        int i   = pin / h;
        int j   = pin - i * h;                 // h%4==0 -> 4-pack same row
        u64 bi = ((u64)i << 40) | 1ull;
        unsigned ax, ay;
        ax = (unsigned)__float2int_rn(fmaf(vx.x, 4096.f, 65536.f));
        ay = (unsigned)__float2int_rn(fmaf(vy.x, 4096.f, 65536.f));
        atomicAdd(&s_xy[lb.x], ((u64)ay << 32) | ax);
        atomicAdd(&s_ij[lb.x], bi | ((u64)(j + 0) << 16));
        ax = (unsigned)__float2int_rn(fmaf(vx.y, 4096.f, 65536.f));
        ay = (unsigned)__float2int_rn(fmaf(vy.y, 4096.f, 65536.f));
        atomicAdd(&s_xy[lb.y], ((u64)ay << 32) | ax);
        atomicAdd(&s_ij[lb.y], bi | ((u64)(j + 1) << 16));
        ax = (unsigned)__float2int_rn(fmaf(vx.z, 4096.f, 65536.f));
        ay = (unsigned)__float2int_rn(fmaf(vy.z, 4096.f, 65536.f));
        atomicAdd(&s_xy[lb.z], ((u64)ay << 32) | ax);
        atomicAdd(&s_ij[lb.z], bi | ((u64)(j + 2) << 16));
        ax = (unsigned)__float2int_rn(fmaf(vx.w, 4096.f, 65536.f));
        ay = (unsigned)__float2int_rn(fmaf(vy.w, 4096.f, 65536.f));
        atomicAdd(&s_xy[lb.w], ((u64)ay << 32) | ax);
        atomicAdd(&s_ij[lb.w], bi | ((u64)(j + 3) << 16));
    }
    __syncthreads();
    for (int q = t; q < K; q += 256) {
        u64 pij = s_ij[q];
        if (!pij) continue;
        unsigned c = (unsigned)(pij & 0xFFFFull);
        float sj = (float)(unsigned)((pij >> 16) & 0xFFFFFFull);
        float si = (float)(unsigned)(pij >> 40);
        u64 pxy = s_xy[q];
        long long ix = (long long)(unsigned)(pxy & 0xFFFFFFFFull) - (long long)c * 65536ll;
        long long iy = (long long)(unsigned)(pxy >> 32)           - (long long)c * 65536ll;
        float fxs = (float)ix * (1.f / 4096.f);
        float fys = (float)iy * (1.f / 4096.f);
        red_v4(&g_sums[b * K + q], fxs, fys, si, sj);
        red_f(&g_cnt[b * K + q], (float)c);
    }
}

// ---- pool fallback: direct global REDs ----
__global__ void pool_gl_k(const int*   __restrict__ labels,
                          const float* __restrict__ fxp,
                          const float* __restrict__ fyp,
                          int P, int h, int K, int Np) {
    int p0 = blockIdx.x * blockDim.x + threadIdx.x;
    if (p0 >= Np) return;
    int b   = p0 / P;
    int pin = p0 - b * P;
    int i   = pin / h;
    int j   = pin - i * h;
    int l   = labels[p0];
    red_v4(&g_sums[b * K + l], fxp[p0], fyp[p0], (float)i, (float)j);
    red_f(&g_cnt[b * K + l], 1.f);
}

// ---- stats: per-token x[5] -> g_x (transposed), accumulate Sx / Sxx^T ----
__global__ void stats_k(const int* __restrict__ fidx,
                        const int* __restrict__ nfp,
                        int K, int BK, float sx, float sy) {
    int tok  = blockIdx.x * 256 + threadIdx.x;
    int lane = threadIdx.x & 31;
    float v[20];
#pragma unroll
    for (int q = 0; q < 20; q++) v[q] = 0.f;
    if (tok < BK) {
        int nf = nfp ? *nfp : 100;
        float invnf = 1.f / (float)(nf - 1);
        int b = tok / K;
        float x0 = (float)__ldg(&fidx[b]) * invnf;
        float cr = g_cnt[tok];
        float ic = 1.f / fmaxf(cr, 1.f);
        float4 s = g_sums[tok];
        float x1 = s.x * ic, x2 = s.y * ic;
        float x3 = (cr > 0.f) ? fmaf(s.z * ic, sx, -1.f) : 0.f;
        float x4 = (cr > 0.f) ? fmaf(s.w * ic, sy, -1.f) : 0.f;
        g_x[tok]          = x0;
        g_x[BK + tok]     = x1;
        g_x[2 * BK + tok] = x2;
        g_x[3 * BK + tok] = x3;
        g_x[4 * BK + tok] = x4;
        float xv[5] = {x0, x1, x2, x3, x4};
        int ix = 0;
#pragma unroll
        for (int d = 0; d < 5; d++) v[ix++] = xv[d];
#pragma unroll
        for (int d = 0; d < 5; d++)
#pragma unroll
            for (int e = d; e < 5; e++) v[ix++] = xv[d] * xv[e];
    }
#pragma unroll
    for (int q = 0; q < 20; q++) {
#pragma unroll
        for (int off = 16; off; off >>= 1)
            v[q] += __shfl_xor_sync(0xffffffffu, v[q], off);
    }
    if (lane == 0) {
#pragma unroll
        for (int q = 0; q < 20; q++) red_f(&g_xstat[q], v[q]);
    }
}

// ---- fused mlp1+mlp2: analytic BN1, conv->relu->linear, BN2 stats ----
__global__ void __launch_bounds__(128) mlp12_k(
        const float* __restrict__ cw,   // [64,5]
        const float* __restrict__ cbp,  // [64]
        const float* __restrict__ g1,
        const float* __restrict__ b1,
        const float* __restrict__ lw,   // [32,64]
        const float* __restrict__ lbp,  // [32]
        int BK, float invN) {
    __shared__ float cw2[320], cb2[64], wsm[2048], lbs[32], xs[20];
    int t = threadIdx.x, lane = t & 31;
    if (t < 20) xs[t] = g_xstat[t];
    for (int q = t; q < 2048; q += 128) wsm[q] = lw[q];
    if (t < 32) lbs[t] = lbp[t];
    __syncthreads();
    if (t < 64) {
        float w[5];
#pragma unroll
        for (int d = 0; d < 5; d++) w[d] = cw[t * 5 + d];
        float m0 = 0.f;
#pragma unroll
        for (int d = 0; d < 5; d++) m0 = fmaf(w[d], xs[d] * invN, m0);
        float q2 = 0.f; int ix = 5;
#pragma unroll
        for (int d = 0; d < 5; d++)
#pragma unroll
            for (int e = d; e < 5; e++) {
                float S = xs[ix++] * invN;
                q2 = fmaf((d == e ? 1.f : 2.f) * w[d] * w[e], S, q2);
            }
        float var = q2 - m0 * m0;                 // Var(w.x)
        float sc  = g1[t] * rsqrtf(var + EPS);
        float ey  = m0 + cbp[t];                  // E[y]
        float sh  = b1[t] - ey * sc;
#pragma unroll
        for (int d = 0; d < 5; d++) cw2[t * 5 + d] = w[d] * sc;
        cb2[t] = fmaf(cbp[t], sc, sh);
    }
    __syncthreads();

    int tok = blockIdx.x * 128 + t;
    bool act = tok < BK;
    float x0 = 0.f, x1 = 0.f, x2 = 0.f, x3 = 0.f, x4 = 0.f;
    if (act) {
        x0 = g_x[tok];          x1 = g_x[BK + tok];
        x2 = g_x[2 * BK + tok]; x3 = g_x[3 * BK + tok];
        x4 = g_x[4 * BK + tok];
    }
    float z[64];
#pragma unroll
    for (int c = 0; c < 64; c++) {
        float y = fmaf(cw2[c*5+4], x4, fmaf(cw2[c*5+3], x3, fmaf(cw2[c*5+2], x2,
                  fmaf(cw2[c*5+1], x1, fmaf(cw2[c*5+0], x0, cb2[c])))));
        z[c] = act ? fmaxf(y, 0.f) : 0.f;
    }
    float o[32];
    const float4* w4 = (const float4*)wsm;
#pragma unroll 4
    for (int oo = 0; oo < 32; oo++) {
        float acc = lbs[oo];
#pragma unroll
        for (int c4 = 0; c4 < 16; c4++) {
            float4 w = w4[oo * 16 + c4];
            acc = fmaf(z[c4*4+0], w.x, fmaf(z[c4*4+1], w.y,
                  fmaf(z[c4*4+2], w.z, fmaf(z[c4*4+3], w.w, acc))));
        }
        o[oo] = act ? acc : 0.f;
        if (act) g_t2[(size_t)oo * BK + tok] = o[oo];
    }
#pragma unroll
    for (int oo = 0; oo < 32; oo++) {
        float s1 = o[oo], s2 = o[oo] * o[oo];
#pragma unroll
        for (int off = 16; off; off >>= 1) {
            s1 += __shfl_xor_sync(0xffffffffu, s1, off);
            s2 += __shfl_xor_sync(0xffffffffu, s2, off);
        }
        if (lane == 0) { red_f(&g_st2[oo], s1); red_f(&g_st2[32 + oo], s2); }
    }
}

// ---- mlp3: BN2+ReLU, in-lane L2 normalize, write output ----
__global__ void mlp3_k(const float* __restrict__ g2,
                       const float* __restrict__ b2,
                       float* __restrict__ out,
                       int BK, float invN) {
    __shared__ float sc[32], sh[32];
    int t = threadIdx.x;
    if (t < 32) {
        float m   = g_st2[t] * invN;
        float var = g_st2[32 + t] * invN - m * m;
        float s   = g2[t] * rsqrtf(var + EPS);
        sc[t] = s; sh[t] = b2[t] - m * s;
    }
    __syncthreads();
    int tok = blockIdx.x * 256 + t;
    if (tok >= BK) return;
    float v[32];
    float n = 0.f;
#pragma unroll
    for (int c = 0; c < 32; c++) {
        float w = g_t2[(size_t)c * BK + tok];
        w = fmaxf(fmaf(w, sc[c], sh[c]), 0.f);
        v[c] = w;
        n = fmaf(w, w, n);
    }
    float inv = 1.f / fmaxf(sqrtf(n), 1e-8f);
    float4* dst = (float4*)(out + (size_t)tok * 32);
#pragma unroll
    for (int q = 0; q < 8; q++)
        dst[q] = make_float4(v[4*q]*inv, v[4*q+1]*inv, v[4*q+2]*inv, v[4*q+3]*inv);
}

extern "C" void kernel_launch(void* const* d_in, const int* in_sizes, int n_in,
                              void* d_out, int out_size) {
    const int*   labels = (const int*)  d_in[0];
    const float* fx     = (const float*)d_in[1];
    const float* fy     = (const float*)d_in[2];
    const int*   fidx   = (const int*)  d_in[3];
    int wi = 4;
    const int* nfp = nullptr;
    if (n_in >= 14) { nfp = (const int*)d_in[4]; wi = 6; }
    const float* cw = (const float*)d_in[wi + 0];
    const float* cb = (const float*)d_in[wi + 1];
    const float* g1 = (const float*)d_in[wi + 2];
    const float* b1 = (const float*)d_in[wi + 3];
    const float* lw = (const float*)d_in[wi + 4];
    const float* lb = (const float*)d_in[wi + 5];
    const float* g2 = (const float*)d_in[wi + 6];
    const float* b2 = (const float*)d_in[wi + 7];

    int B  = in_sizes[3];
    int Np = in_sizes[0];
    int P  = Np / B;
    int BK = out_size / 32;
    int K  = BK / B;
    int hh = (int)(sqrt((double)P) + 0.5);
    int ww = P / hh;
    float sx = 2.f / (float)(ww - 1);
    float sy = 2.f / (float)(hh - 1);

    zero_k<<<(BK + 255) / 256, 256>>>(BK);

    bool fast = (hh * ww == P) && (hh % 4 == 0) && (P % CHUNK == 0) &&
                (K <= 2048) && (hh <= 1024) && (ww <= 1024);
    if (fast) {
        int cpb = P / CHUNK;
        pool_priv_k<<<B * cpb, 256, (size_t)K * 16>>>(labels, fx, fy, P, hh, K, cpb);
    } else {
        pool_gl_k<<<(Np + 255) / 256, 256>>>(labels, fx, fy, P, hh, K, Np);
    }

    float invN = 1.f / (float)BK;
    stats_k<<<(BK + 255) / 256, 256>>>(fidx, nfp, K, BK, sx, sy);
    mlp12_k<<<(BK + 127) / 128, 128>>>(cw, cb, g1, b1, lw, lb, BK, invN);
    mlp3_k<<<(BK + 255) / 256, 256>>>(g2, b2, (float*)d_out, BK, invN);
}

// round 6
// speedup vs baseline: 1.0966x; 1.0966x over previous
#include <cuda_runtime.h>
#include <math.h>

#define EPS 1e-5f
#define MAX_BK 32768
typedef unsigned long long u64;

// ---- scratch (device globals) ----
__device__ float4 g_sums[MAX_BK];           // per-bin {sum fx, sum fy, sum_i, sum_j}
__device__ float  g_cnt [MAX_BK];
__device__ float  g_x  [(size_t)5  * MAX_BK];   // feature-major token features [5][BK]
__device__ float  g_t2 [(size_t)MAX_BK * 32];   // token-major layer-2 pre-BN [BK][32]
__device__ float  g_xstat[20];              // Sx(5) + upper-tri Sxx(15)
__device__ float  g_st2[64];                // [0:32) sum, [32:64) sumsq layer-2

__device__ __forceinline__ void red_v4(float4* p, float a, float b, float c, float d) {
    asm volatile("red.global.add.v4.f32 [%0], {%1,%2,%3,%4};"
                 :: "l"(p), "f"(a), "f"(b), "f"(c), "f"(d) : "memory");
}
__device__ __forceinline__ void red_f(float* p, float v) {
    asm volatile("red.global.add.f32 [%0], %1;" :: "l"(p), "f"(v) : "memory");
}

// ---- kernel 0: zero accumulators ----
__global__ void zero_k(int bk) {
    int i = blockIdx.x * blockDim.x + threadIdx.x;
    if (i < bk) { g_sums[i] = make_float4(0.f, 0.f, 0.f, 0.f); g_cnt[i] = 0.f; }
    if (i < 20) g_xstat[i] = 0.f;
    if (i < 64) g_st2[i] = 0.f;
}

// ---- pool (fast path): exact round-3 version. CTA = 4096 pixels of one image ----
__global__ void pool_priv_k(const int*   __restrict__ labels,
                            const float* __restrict__ fxp,
                            const float* __restrict__ fyp,
                            int P, int h, int K, int cpb) {
    extern __shared__ char sm[];
    u64*   s_ij = (u64*)sm;                 // [K]
    float* s_fx = (float*)(sm + (size_t)K * 8);
    float* s_fy = s_fx + K;
    int t = threadIdx.x;
    for (int q = t; q < K; q += 256) { s_ij[q] = 0ull; s_fx[q] = 0.f; s_fy[q] = 0.f; }
    __syncthreads();

    int b     = blockIdx.x / cpb;
    int chunk = blockIdx.x - b * cpb;
    int base4 = (b * P + chunk * 4096) >> 2;
#pragma unroll
    for (int it = 0; it < 4; it++) {
        int g4 = base4 + it * 256 + t;
        int4   lb = ((const int4*)  labels)[g4];
        float4 vx = ((const float4*)fxp)[g4];
        float4 vy = ((const float4*)fyp)[g4];
        int p0  = g4 << 2;
        int pin = p0 - b * P;
        int i   = pin / h;
        int j   = pin - i * h;              // h % 4 == 0 -> 4-pack same row
        u64 bi = ((u64)i << 40) | 1ull;
        atomicAdd(&s_fx[lb.x], vx.x); atomicAdd(&s_fy[lb.x], vy.x);
        atomicAdd(&s_ij[lb.x], bi | ((u64)(j + 0) << 16));
        atomicAdd(&s_fx[lb.y], vx.y); atomicAdd(&s_fy[lb.y], vy.y);
        atomicAdd(&s_ij[lb.y], bi | ((u64)(j + 1) << 16));
        atomicAdd(&s_fx[lb.z], vx.z); atomicAdd(&s_fy[lb.z], vy.z);
        atomicAdd(&s_ij[lb.z], bi | ((u64)(j + 2) << 16));
        atomicAdd(&s_fx[lb.w], vx.w); atomicAdd(&s_fy[lb.w], vy.w);
        atomicAdd(&s_ij[lb.w], bi | ((u64)(j + 3) << 16));
    }
    __syncthreads();
    for (int q = t; q < K; q += 256) {
        u64 p = s_ij[q];
        if (p) {
            float si = (float)(unsigned)(p >> 40);
            float sj = (float)(unsigned)((p >> 16) & 0xFFFFFFull);
            float c  = (float)(unsigned)(p & 0xFFFFull);
            red_v4(&g_sums[b * K + q], s_fx[q], s_fy[q], si, sj);
            red_f(&g_cnt[b * K + q], c);
        }
    }
}

// ---- pool fallback: direct global REDs ----
__global__ void pool_gl_k(const int*   __restrict__ labels,
                          const float* __restrict__ fxp,
                          const float* __restrict__ fyp,
                          int P, int h, int K, int Np) {
    int p0 = blockIdx.x * blockDim.x + threadIdx.x;
    if (p0 >= Np) return;
    int b   = p0 / P;
    int pin = p0 - b * P;
    int i   = pin / h;
    int j   = pin - i * h;
    int l   = labels[p0];
    red_v4(&g_sums[b * K + l], fxp[p0], fyp[p0], (float)i, (float)j);
    red_f(&g_cnt[b * K + l], 1.f);
}

// ---- stats: per-token x[5] -> g_x (feature-major), accumulate Sx / Sxx ----
__global__ void stats_k(const int* __restrict__ fidx,
                        const int* __restrict__ nfp,
                        int K, int BK, float sx, float sy) {
    int tok  = blockIdx.x * 256 + threadIdx.x;
    int lane = threadIdx.x & 31;
    float v[20];
#pragma unroll
    for (int q = 0; q < 20; q++) v[q] = 0.f;
    if (tok < BK) {
        int nf = nfp ? *nfp : 100;
        float invnf = 1.f / (float)(nf - 1);
        int b = tok / K;
        float x0 = (float)__ldg(&fidx[b]) * invnf;
        float cr = g_cnt[tok];
        float ic = 1.f / fmaxf(cr, 1.f);
        float4 s = g_sums[tok];
        float x1 = s.x * ic, x2 = s.y * ic;
        float x3 = (cr > 0.f) ? fmaf(s.z * ic, sx, -1.f) : 0.f;
        float x4 = (cr > 0.f) ? fmaf(s.w * ic, sy, -1.f) : 0.f;
        g_x[tok]          = x0;
        g_x[BK + tok]     = x1;
        g_x[2 * BK + tok] = x2;
        g_x[3 * BK + tok] = x3;
        g_x[4 * BK + tok] = x4;
        float xv[5] = {x0, x1, x2, x3, x4};
        int ix = 0;
#pragma unroll
        for (int d = 0; d < 5; d++) v[ix++] = xv[d];
#pragma unroll
        for (int d = 0; d < 5; d++)
#pragma unroll
            for (int e = d; e < 5; e++) v[ix++] = xv[d] * xv[e];
    }
#pragma unroll
    for (int q = 0; q < 20; q++) {
#pragma unroll
        for (int off = 16; off; off >>= 1)
            v[q] += __shfl_xor_sync(0xffffffffu, v[q], off);
    }
    if (lane == 0) {
#pragma unroll
        for (int q = 0; q < 20; q++) red_f(&g_xstat[q], v[q]);
    }
}

// ---- fused mlp1+mlp2: warp per 8 tokens, lane = output channel, weights in regs ----
// Staging fix vs round 5: xa holds features 0..3 (lane = f*8 + tok, 32 lanes),
// xb holds feature 4 on lanes 0..7. x4 = shfl(xb, tt).
__global__ void __launch_bounds__(256) mlp12_k(
        const float* __restrict__ cw,   // [64,5]
        const float* __restrict__ cbp,  // [64]
        const float* __restrict__ g1,
        const float* __restrict__ b1,
        const float* __restrict__ lw,   // [32,64]
        const float* __restrict__ lbp,  // [32]
        int BK, float invN) {
    __shared__ float xs[20];
    __shared__ float ssum[32], ssq[32];
    int t = threadIdx.x, lane = t & 31, w = t >> 5;
    if (t < 20) xs[t] = g_xstat[t];
    if (t < 32) { ssum[t] = 0.f; ssq[t] = 0.f; }
    __syncthreads();

    // per-lane folded-BN1 conv weights for channels lane (lo) and lane+32 (hi)
    float cwlo[5], cwhi[5], cblo, cbhi;
#pragma unroll
    for (int hh = 0; hh < 2; hh++) {
        int ch = lane + 32 * hh;
        float wv[5];
#pragma unroll
        for (int d = 0; d < 5; d++) wv[d] = __ldg(&cw[ch * 5 + d]);
        float bv = __ldg(&cbp[ch]);
        float m0 = 0.f;
#pragma unroll
        for (int d = 0; d < 5; d++) m0 = fmaf(wv[d], xs[d] * invN, m0);
        float q2 = 0.f; int ix = 5;
#pragma unroll
        for (int d = 0; d < 5; d++)
#pragma unroll
            for (int e = d; e < 5; e++) {
                float S = xs[ix++] * invN;
                q2 = fmaf((d == e ? 1.f : 2.f) * wv[d] * wv[e], S, q2);
            }
        float var = q2 - m0 * m0;                 // Var of pre-BN channel
        float sc  = __ldg(&g1[ch]) * rsqrtf(var + EPS);
        // E[y] = m0 + bv; folded: y_bn = (w.x + bv)*sc + (b1 - E[y]*sc)
        float cbf = fmaf(bv, sc, __ldg(&b1[ch]) - (m0 + bv) * sc);
        if (hh == 0) {
#pragma unroll
            for (int d = 0; d < 5; d++) cwlo[d] = wv[d] * sc;
            cblo = cbf;
        } else {
#pragma unroll
            for (int d = 0; d < 5; d++) cwhi[d] = wv[d] * sc;
            cbhi = cbf;
        }
    }

    // lane's linear-layer weight row in registers
    float wreg[64];
#pragma unroll
    for (int c = 0; c < 64; c++) wreg[c] = __ldg(&lw[lane * 64 + c]);
    float lbias = __ldg(&lbp[lane]);

    int tok0 = (blockIdx.x * 8 + w) * 8;
    // stage: xa = feature (lane>>3) of token tok0+(lane&7);  xb = feature 4 (lanes 0..7)
    float xa, xb = 0.f;
    {
        int tk = tok0 + (lane & 7);
        if (tk >= BK) tk = BK - 1;
        xa = g_x[(size_t)(lane >> 3) * BK + tk];
        int tk2 = tok0 + lane;
        if (lane < 8) {
            int tkc = (tk2 < BK) ? tk2 : BK - 1;
            xb = g_x[(size_t)4 * BK + tkc];
        }
    }
    float s1 = 0.f, s2 = 0.f;
#pragma unroll 2
    for (int tt = 0; tt < 8; tt++) {
        float x0 = __shfl_sync(0xffffffffu, xa, tt);
        float x1 = __shfl_sync(0xffffffffu, xa, 8 + tt);
        float x2 = __shfl_sync(0xffffffffu, xa, 16 + tt);
        float x3 = __shfl_sync(0xffffffffu, xa, 24 + tt);
        float x4 = __shfl_sync(0xffffffffu, xb, tt);
        float zlo = fmaxf(fmaf(cwlo[4], x4, fmaf(cwlo[3], x3, fmaf(cwlo[2], x2,
                    fmaf(cwlo[1], x1, fmaf(cwlo[0], x0, cblo))))), 0.f);
        float zhi = fmaxf(fmaf(cwhi[4], x4, fmaf(cwhi[3], x3, fmaf(cwhi[2], x2,
                    fmaf(cwhi[1], x1, fmaf(cwhi[0], x0, cbhi))))), 0.f);
        float acc = lbias;
#pragma unroll
        for (int c = 0; c < 32; c++)
            acc = fmaf(__shfl_sync(0xffffffffu, zlo, c), wreg[c], acc);
#pragma unroll
        for (int c = 0; c < 32; c++)
            acc = fmaf(__shfl_sync(0xffffffffu, zhi, c), wreg[32 + c], acc);
        int tok = tok0 + tt;
        if (tok < BK) {
            g_t2[(size_t)tok * 32 + lane] = acc;
            s1 += acc; s2 = fmaf(acc, acc, s2);
        }
    }
    atomicAdd(&ssum[lane], s1);
    atomicAdd(&ssq[lane], s2);
    __syncthreads();
    if (t < 32) { red_f(&g_st2[t], ssum[t]); red_f(&g_st2[32 + t], ssq[t]); }
}

// ---- mlp3: warp per 8 tokens, lane = channel; butterfly norm; coalesced I/O ----
__global__ void mlp3_k(const float* __restrict__ g2,
                       const float* __restrict__ b2,
                       float* __restrict__ out,
                       int BK, float invN) {
    __shared__ float sc[32], sh[32];
    int t = threadIdx.x, lane = t & 31, w = t >> 5;
    if (t < 32) {
        float m   = g_st2[t] * invN;
        float var = g_st2[32 + t] * invN - m * m;
        float s   = g2[t] * rsqrtf(var + EPS);
        sc[t] = s; sh[t] = b2[t] - m * s;
    }
    __syncthreads();
    float scl = sc[lane], shl = sh[lane];
    int tok0 = (blockIdx.x * 8 + w) * 8;
    float v[8];
#pragma unroll
    for (int tt = 0; tt < 8; tt++) {
        int tok = tok0 + tt;
        v[tt] = (tok < BK) ? g_t2[(size_t)tok * 32 + lane] : 0.f;
    }
#pragma unroll
    for (int tt = 0; tt < 8; tt++) {
        float x = fmaxf(fmaf(v[tt], scl, shl), 0.f);
        float n = x * x;
#pragma unroll
        for (int off = 16; off; off >>= 1)
            n += __shfl_xor_sync(0xffffffffu, n, off);
        float inv = 1.f / fmaxf(sqrtf(n), 1e-8f);
        int tok = tok0 + tt;
        if (tok < BK) out[(size_t)tok * 32 + lane] = x * inv;
    }
}

extern "C" void kernel_launch(void* const* d_in, const int* in_sizes, int n_in,
                              void* d_out, int out_size) {
    const int*   labels = (const int*)  d_in[0];
    const float* fx     = (const float*)d_in[1];
    const float* fy     = (const float*)d_in[2];
    const int*   fidx   = (const int*)  d_in[3];
    int wi = 4;
    const int* nfp = nullptr;
    if (n_in >= 14) { nfp = (const int*)d_in[4]; wi = 6; }
    const float* cw = (const float*)d_in[wi + 0];
    const float* cb = (const float*)d_in[wi + 1];
    const float* g1 = (const float*)d_in[wi + 2];
    const float* b1 = (const float*)d_in[wi + 3];
    const float* lw = (const float*)d_in[wi + 4];
    const float* lb = (const float*)d_in[wi + 5];
    const float* g2 = (const float*)d_in[wi + 6];
    const float* b2 = (const float*)d_in[wi + 7];

    int B  = in_sizes[3];
    int Np = in_sizes[0];
    int P  = Np / B;
    int BK = out_size / 32;
    int K  = BK / B;
    int hh = (int)(sqrt((double)P) + 0.5);
    int ww = P / hh;
    float sx = 2.f / (float)(ww - 1);
    float sy = 2.f / (float)(hh - 1);

    zero_k<<<(BK + 255) / 256, 256>>>(BK);

    bool fast = (hh * ww == P) && (hh % 4 == 0) && (P % 4096 == 0) &&
                (K <= 2048) && (hh <= 4096) && (ww <= 4096);
    if (fast) {
        int cpb = P / 4096;
        pool_priv_k<<<B * cpb, 256, (size_t)K * 16>>>(labels, fx, fy, P, hh, K, cpb);
    } else {
        pool_gl_k<<<(Np + 255) / 256, 256>>>(labels, fx, fy, P, hh, K, Np);
    }

    float invN = 1.f / (float)BK;
    stats_k<<<(BK + 255) / 256, 256>>>(fidx, nfp, K, BK, sx, sy);
    int gb64 = (BK + 63) / 64;
    mlp12_k<<<gb64, 256>>>(cw, cb, g1, b1, lw, lb, BK, invN);
    mlp3_k<<<gb64, 256>>>(g2, b2, (float*)d_out, BK, invN);
}

// round 7
// speedup vs baseline: 1.3610x; 1.2412x over previous
#include <cuda_runtime.h>
#include <math.h>

#define EPS 1e-5f
#define MAX_BK 32768
typedef unsigned long long u64;

// ---- scratch (device globals) ----
__device__ float4 g_sums[MAX_BK];           // per-bin {sum fx, sum fy, sum_i, sum_j}
__device__ float  g_cnt [MAX_BK];
__device__ float  g_x  [(size_t)5  * MAX_BK];   // feature-major token features [5][BK]
__device__ float  g_t2 [(size_t)MAX_BK * 32];   // token-major layer-2 pre-BN [BK][32]
__device__ float  g_xstat[20];              // Sx(5) + upper-tri Sxx(15)
__device__ float  g_st2[64];                // [0:32) sum, [32:64) sumsq layer-2

__device__ __forceinline__ void red_v4(float4* p, float a, float b, float c, float d) {
    asm volatile("red.global.add.v4.f32 [%0], {%1,%2,%3,%4};"
                 :: "l"(p), "f"(a), "f"(b), "f"(c), "f"(d) : "memory");
}
__device__ __forceinline__ void red_f(float* p, float v) {
    asm volatile("red.global.add.f32 [%0], %1;" :: "l"(p), "f"(v) : "memory");
}

// ---- kernel 0: zero accumulators ----
__global__ void zero_k(int bk) {
    int i = blockIdx.x * blockDim.x + threadIdx.x;
    if (i < bk) { g_sums[i] = make_float4(0.f, 0.f, 0.f, 0.f); g_cnt[i] = 0.f; }
    if (i < 20) g_xstat[i] = 0.f;
    if (i < 64) g_st2[i] = 0.f;
}

// ---- pool (fast path): exact round-3 version. CTA = 4096 pixels of one image ----
__global__ void pool_priv_k(const int*   __restrict__ labels,
                            const float* __restrict__ fxp,
                            const float* __restrict__ fyp,
                            int P, int h, int K, int cpb) {
    extern __shared__ char sm[];
    u64*   s_ij = (u64*)sm;                 // [K]
    float* s_fx = (float*)(sm + (size_t)K * 8);
    float* s_fy = s_fx + K;
    int t = threadIdx.x;
    for (int q = t; q < K; q += 256) { s_ij[q] = 0ull; s_fx[q] = 0.f; s_fy[q] = 0.f; }
    __syncthreads();

    int b     = blockIdx.x / cpb;
    int chunk = blockIdx.x - b * cpb;
    int base4 = (b * P + chunk * 4096) >> 2;
#pragma unroll
    for (int it = 0; it < 4; it++) {
        int g4 = base4 + it * 256 + t;
        int4   lb = ((const int4*)  labels)[g4];
        float4 vx = ((const float4*)fxp)[g4];
        float4 vy = ((const float4*)fyp)[g4];
        int p0  = g4 << 2;
        int pin = p0 - b * P;
        int i   = pin / h;
        int j   = pin - i * h;              // h % 4 == 0 -> 4-pack same row
        u64 bi = ((u64)i << 40) | 1ull;
        atomicAdd(&s_fx[lb.x], vx.x); atomicAdd(&s_fy[lb.x], vy.x);
        atomicAdd(&s_ij[lb.x], bi | ((u64)(j + 0) << 16));
        atomicAdd(&s_fx[lb.y], vx.y); atomicAdd(&s_fy[lb.y], vy.y);
        atomicAdd(&s_ij[lb.y], bi | ((u64)(j + 1) << 16));
        atomicAdd(&s_fx[lb.z], vx.z); atomicAdd(&s_fy[lb.z], vy.z);
        atomicAdd(&s_ij[lb.z], bi | ((u64)(j + 2) << 16));
        atomicAdd(&s_fx[lb.w], vx.w); atomicAdd(&s_fy[lb.w], vy.w);
        atomicAdd(&s_ij[lb.w], bi | ((u64)(j + 3) << 16));
    }
    __syncthreads();
    for (int q = t; q < K; q += 256) {
        u64 p = s_ij[q];
        if (p) {
            float si = (float)(unsigned)(p >> 40);
            float sj = (float)(unsigned)((p >> 16) & 0xFFFFFFull);
            float c  = (float)(unsigned)(p & 0xFFFFull);
            red_v4(&g_sums[b * K + q], s_fx[q], s_fy[q], si, sj);
            red_f(&g_cnt[b * K + q], c);
        }
    }
}

// ---- pool fallback: direct global REDs ----
__global__ void pool_gl_k(const int*   __restrict__ labels,
                          const float* __restrict__ fxp,
                          const float* __restrict__ fyp,
                          int P, int h, int K, int Np) {
    int p0 = blockIdx.x * blockDim.x + threadIdx.x;
    if (p0 >= Np) return;
    int b   = p0 / P;
    int pin = p0 - b * P;
    int i   = pin / h;
    int j   = pin - i * h;
    int l   = labels[p0];
    red_v4(&g_sums[b * K + l], fxp[p0], fyp[p0], (float)i, (float)j);
    red_f(&g_cnt[b * K + l], 1.f);
}

// ---- stats: per-token x[5] -> g_x (feature-major), accumulate Sx / Sxx ----
__global__ void stats_k(const int* __restrict__ fidx,
                        const int* __restrict__ nfp,
                        int K, int BK, float sx, float sy) {
    int tok  = blockIdx.x * 256 + threadIdx.x;
    int lane = threadIdx.x & 31;
    float v[20];
#pragma unroll
    for (int q = 0; q < 20; q++) v[q] = 0.f;
    if (tok < BK) {
        int nf = nfp ? *nfp : 100;
        float invnf = 1.f / (float)(nf - 1);
        int b = tok / K;
        float x0 = (float)__ldg(&fidx[b]) * invnf;
        float cr = g_cnt[tok];
        float ic = 1.f / fmaxf(cr, 1.f);
        float4 s = g_sums[tok];
        float x1 = s.x * ic, x2 = s.y * ic;
        float x3 = (cr > 0.f) ? fmaf(s.z * ic, sx, -1.f) : 0.f;
        float x4 = (cr > 0.f) ? fmaf(s.w * ic, sy, -1.f) : 0.f;
        g_x[tok]          = x0;
        g_x[BK + tok]     = x1;
        g_x[2 * BK + tok] = x2;
        g_x[3 * BK + tok] = x3;
        g_x[4 * BK + tok] = x4;
        float xv[5] = {x0, x1, x2, x3, x4};
        int ix = 0;
#pragma unroll
        for (int d = 0; d < 5; d++) v[ix++] = xv[d];
#pragma unroll
        for (int d = 0; d < 5; d++)
#pragma unroll
            for (int e = d; e < 5; e++) v[ix++] = xv[d] * xv[e];
    }
#pragma unroll
    for (int q = 0; q < 20; q++) {
#pragma unroll
        for (int off = 16; off; off >>= 1)
            v[q] += __shfl_xor_sync(0xffffffffu, v[q], off);
    }
    if (lane == 0) {
#pragma unroll
        for (int q = 0; q < 20; q++) red_f(&g_xstat[q], v[q]);
    }
}

// ---- fused mlp1+mlp2: thread = (token, half). z in register chunks, weights via
// broadcast LDS.128, zero shuffles. BN2 stats via conflict-free smem transpose. ----
__global__ void __launch_bounds__(128) mlp12_k(
        const float* __restrict__ cw,   // [64,5]
        const float* __restrict__ cbp,  // [64]
        const float* __restrict__ g1,
        const float* __restrict__ b1,
        const float* __restrict__ lw,   // [32,64]
        const float* __restrict__ lbp,  // [32]
        int BK, float invN) {
    __shared__ float xs[20];
    __shared__ float cw2p[512];          // folded conv coefs, 8 floats/ch: w0..w4, cb, pad, pad
    __shared__ float wsm[2048];          // lw [32][64]
    __shared__ float lbs[32];
    __shared__ float ssum[32], ssq[32];
    __shared__ float tile[4 * 528];      // per-warp 16 tokens x 33-stride transpose pad

    int t = threadIdx.x, lane = t & 31, w = t >> 5;
    if (t < 20) xs[t] = g_xstat[t];
    if (t < 32) { lbs[t] = __ldg(&lbp[t]); ssum[t] = 0.f; ssq[t] = 0.f; }
    for (int q = t; q < 2048; q += 128) wsm[q] = __ldg(&lw[q]);
    __syncthreads();
    if (t < 64) {
        int ch = t;
        float wv[5];
#pragma unroll
        for (int d = 0; d < 5; d++) wv[d] = __ldg(&cw[ch * 5 + d]);
        float bv = __ldg(&cbp[ch]);
        float m0 = 0.f;
#pragma unroll
        for (int d = 0; d < 5; d++) m0 = fmaf(wv[d], xs[d] * invN, m0);
        float q2 = 0.f; int ix = 5;
#pragma unroll
        for (int d = 0; d < 5; d++)
#pragma unroll
            for (int e = d; e < 5; e++) {
                float S = xs[ix++] * invN;
                q2 = fmaf((d == e ? 1.f : 2.f) * wv[d] * wv[e], S, q2);
            }
        float var = q2 - m0 * m0;
        float sc  = __ldg(&g1[ch]) * rsqrtf(var + EPS);
        float cbf = fmaf(bv, sc, __ldg(&b1[ch]) - (m0 + bv) * sc);
#pragma unroll
        for (int d = 0; d < 5; d++) cw2p[ch * 8 + d] = wv[d] * sc;
        cw2p[ch * 8 + 5] = cbf;
        cw2p[ch * 8 + 6] = 0.f;
        cw2p[ch * 8 + 7] = 0.f;
    }
    __syncthreads();

    int tok = blockIdx.x * 64 + (t >> 1);
    int hf  = t & 1;                     // which half of the 32 outputs
    bool act = tok < BK;
    int tclamp = act ? tok : (BK - 1);
    float x0 = g_x[tclamp];
    float x1 = g_x[BK + tclamp];
    float x2 = g_x[2 * BK + tclamp];
    float x3 = g_x[3 * BK + tclamp];
    float x4 = g_x[4 * BK + tclamp];

    float o[16];
#pragma unroll
    for (int c = 0; c < 16; c++) o[c] = lbs[hf * 16 + c];

    const float4* cw4 = (const float4*)cw2p;
    const float4* w4  = (const float4*)wsm;
#pragma unroll
    for (int chunk = 0; chunk < 4; chunk++) {
        float z[16];
#pragma unroll
        for (int c = 0; c < 16; c++) {
            int ch = chunk * 16 + c;
            float4 a = cw4[ch * 2];
            float4 b = cw4[ch * 2 + 1];
            float v = fmaf(a.x, x0, fmaf(a.y, x1, fmaf(a.z, x2,
                      fmaf(a.w, x3, fmaf(b.x, x4, b.y)))));
            z[c] = fmaxf(v, 0.f);
        }
#pragma unroll
        for (int cc = 0; cc < 16; cc++) {
            int row = (hf * 16 + cc) * 16 + chunk * 4;
#pragma unroll
            for (int q = 0; q < 4; q++) {
                float4 ww = w4[row + q];
                o[cc] = fmaf(z[q*4+0], ww.x, fmaf(z[q*4+1], ww.y,
                        fmaf(z[q*4+2], ww.z, fmaf(z[q*4+3], ww.w, o[cc]))));
            }
        }
    }
    if (!act) {
#pragma unroll
        for (int c = 0; c < 16; c++) o[c] = 0.f;
    }
    if (act) {
        float4* dst = (float4*)&g_t2[(size_t)tok * 32 + hf * 16];
#pragma unroll
        for (int q = 0; q < 4; q++)
            dst[q] = make_float4(o[4*q], o[4*q+1], o[4*q+2], o[4*q+3]);
    }

    // BN2 stats: smem transpose per warp (16 tokens x 32 channels, stride 33)
    float* tw = tile + w * 528;
    int tokin = (t >> 1) & 15;
#pragma unroll
    for (int c = 0; c < 16; c++)
        tw[tokin * 33 + hf * 16 + c] = o[c];
    __syncwarp();
    float s1 = 0.f, s2 = 0.f;
#pragma unroll
    for (int i = 0; i < 16; i++) {
        float v = tw[i * 33 + lane];
        s1 += v; s2 = fmaf(v, v, s2);
    }
    atomicAdd(&ssum[lane], s1);
    atomicAdd(&ssq[lane], s2);
    __syncthreads();
    if (t < 32) { red_f(&g_st2[t], ssum[t]); red_f(&g_st2[32 + t], ssq[t]); }
}

// ---- mlp3: warp per 8 tokens, lane = channel; butterfly norm; coalesced I/O ----
__global__ void mlp3_k(const float* __restrict__ g2,
                       const float* __restrict__ b2,
                       float* __restrict__ out,
                       int BK, float invN) {
    __shared__ float sc[32], sh[32];
    int t = threadIdx.x, lane = t & 31, w = t >> 5;
    if (t < 32) {
        float m   = g_st2[t] * invN;
        float var = g_st2[32 + t] * invN - m * m;
        float s   = g2[t] * rsqrtf(var + EPS);
        sc[t] = s; sh[t] = b2[t] - m * s;
    }
    __syncthreads();
    float scl = sc[lane], shl = sh[lane];
    int tok0 = (blockIdx.x * 8 + w) * 8;
    float v[8];
#pragma unroll
    for (int tt = 0; tt < 8; tt++) {
        int tok = tok0 + tt;
        v[tt] = (tok < BK) ? g_t2[(size_t)tok * 32 + lane] : 0.f;
    }
#pragma unroll
    for (int tt = 0; tt < 8; tt++) {
        float x = fmaxf(fmaf(v[tt], scl, shl), 0.f);
        float n = x * x;
#pragma unroll
        for (int off = 16; off; off >>= 1)
            n += __shfl_xor_sync(0xffffffffu, n, off);
        float inv = 1.f / fmaxf(sqrtf(n), 1e-8f);
        int tok = tok0 + tt;
        if (tok < BK) out[(size_t)tok * 32 + lane] = x * inv;
    }
}

extern "C" void kernel_launch(void* const* d_in, const int* in_sizes, int n_in,
                              void* d_out, int out_size) {
    const int*   labels = (const int*)  d_in[0];
    const float* fx     = (const float*)d_in[1];
    const float* fy     = (const float*)d_in[2];
    const int*   fidx   = (const int*)  d_in[3];
    int wi = 4;
    const int* nfp = nullptr;
    if (n_in >= 14) { nfp = (const int*)d_in[4]; wi = 6; }
    const float* cw = (const float*)d_in[wi + 0];
    const float* cb = (const float*)d_in[wi + 1];
    const float* g1 = (const float*)d_in[wi + 2];
    const float* b1 = (const float*)d_in[wi + 3];
    const float* lw = (const float*)d_in[wi + 4];
    const float* lb = (const float*)d_in[wi + 5];
    const float* g2 = (const float*)d_in[wi + 6];
    const float* b2 = (const float*)d_in[wi + 7];

    int B  = in_sizes[3];
    int Np = in_sizes[0];
    int P  = Np / B;
    int BK = out_size / 32;
    int K  = BK / B;
    int hh = (int)(sqrt((double)P) + 0.5);
    int ww = P / hh;
    float sx = 2.f / (float)(ww - 1);
    float sy = 2.f / (float)(hh - 1);

    zero_k<<<(BK + 255) / 256, 256>>>(BK);

    bool fast = (hh * ww == P) && (hh % 4 == 0) && (P % 4096 == 0) &&
                (K <= 2048) && (hh <= 4096) && (ww <= 4096);
    if (fast) {
        int cpb = P / 4096;
        pool_priv_k<<<B * cpb, 256, (size_t)K * 16>>>(labels, fx, fy, P, hh, K, cpb);
    } else {
        pool_gl_k<<<(Np + 255) / 256, 256>>>(labels, fx, fy, P, hh, K, Np);
    }

    float invN = 1.f / (float)BK;
    stats_k<<<(BK + 255) / 256, 256>>>(fidx, nfp, K, BK, sx, sy);
    mlp12_k<<<(BK + 63) / 64, 128>>>(cw, cb, g1, b1, lw, lb, BK, invN);
    mlp3_k<<<(BK + 63) / 64, 256>>>(g2, b2, (float*)d_out, BK, invN);
}